// round 1
// baseline (speedup 1.0000x reference)
#include <cuda_runtime.h>

#define NNODES 50000
#define NEDGES 800000
#define FDIM   128
#define NEG_SLOPE 0.2f

// ---------------- scratch (device globals: allocation-free) ----------------
__device__ float g_xl[NNODES * FDIM];   // lin_l output (messages)
__device__ float g_xr[NNODES * FDIM];   // lin_r output (target transform)
__device__ float g_h [NNODES * FDIM];   // layer-1 output
__device__ int   g_deg[NNODES];
__device__ int   g_cursor[NNODES];
__device__ int   g_rowptr[NNODES + 1];
__device__ int   g_csrc[NEDGES];        // CSR-by-dst: source node per slot

// ---------------- CSR build ----------------
__global__ void zero_deg_kernel() {
    int i = blockIdx.x * blockDim.x + threadIdx.x;
    if (i < NNODES) g_deg[i] = 0;
}

__global__ void count_kernel(const int* __restrict__ dst) {
    int e = blockIdx.x * blockDim.x + threadIdx.x;
    if (e < NEDGES) atomicAdd(&g_deg[dst[e]], 1);
}

// single-block exclusive scan over 50000 degrees (Hillis-Steele chunks)
__global__ void scan_kernel() {
    __shared__ int sm[1024];
    __shared__ int s_carry;
    int tid = threadIdx.x;
    if (tid == 0) s_carry = 0;
    __syncthreads();
    for (int base = 0; base < NNODES; base += 1024) {
        int i = base + tid;
        int v = (i < NNODES) ? g_deg[i] : 0;
        int val = v;
        sm[tid] = val;
        __syncthreads();
        #pragma unroll
        for (int off = 1; off < 1024; off <<= 1) {
            int t = (tid >= off) ? sm[tid - off] : 0;
            __syncthreads();
            val += t;
            sm[tid] = val;
            __syncthreads();
        }
        int excl = s_carry + val - v;
        if (i < NNODES) { g_rowptr[i] = excl; g_cursor[i] = excl; }
        __syncthreads();                 // all reads of s_carry done
        if (tid == 1023) s_carry += sm[1023];
        __syncthreads();
    }
    if (tid == 0) g_rowptr[NNODES] = s_carry;
}

__global__ void scatter_kernel(const int* __restrict__ src, const int* __restrict__ dst) {
    int e = blockIdx.x * blockDim.x + threadIdx.x;
    if (e < NEDGES) {
        int p = atomicAdd(&g_cursor[dst[e]], 1);
        g_csrc[p] = src[e];
    }
}

// ---------------- dual GEMM: computes g_xl = A@Wl+bl and g_xr = A@Wr+br ----
// BM=BN=128, BK=8, 256 threads, 8x8 per thread. blockIdx.y selects (Wl)/(Wr).
__global__ __launch_bounds__(256) void gemm_dual_kernel(
    const float* __restrict__ Aarg, int use_h,
    const float* __restrict__ Wl, const float* __restrict__ bl,
    const float* __restrict__ Wr, const float* __restrict__ br)
{
    const float* A    = use_h ? g_h : Aarg;
    const float* W    = blockIdx.y ? Wr : Wl;
    const float* bias = blockIdx.y ? br : bl;
    float*       out  = blockIdx.y ? g_xr : g_xl;

    __shared__ float As[8][128];
    __shared__ float Bs[8][128];

    const int t    = threadIdx.x;
    const int row0 = blockIdx.x * 128;
    const int tx   = t & 15;           // 0..15 -> 8 output cols each
    const int ty   = t >> 4;           // 0..15 -> 8 output rows each

    const int aRow = t >> 1;           // 0..127
    const int aK   = (t & 1) * 4;      // 0 or 4
    const int bK   = t >> 5;           // 0..7
    const int bCol = (t & 31) * 4;     // 0..124

    float c[8][8];
    #pragma unroll
    for (int i = 0; i < 8; i++)
        #pragma unroll
        for (int j = 0; j < 8; j++) c[i][j] = 0.f;

    const int gr_a = row0 + aRow;
    for (int kc = 0; kc < FDIM; kc += 8) {
        float4 a4;
        if (gr_a < NNODES) a4 = *(const float4*)(A + gr_a * FDIM + kc + aK);
        else               a4 = make_float4(0.f, 0.f, 0.f, 0.f);
        As[aK + 0][aRow] = a4.x;
        As[aK + 1][aRow] = a4.y;
        As[aK + 2][aRow] = a4.z;
        As[aK + 3][aRow] = a4.w;
        *(float4*)&Bs[bK][bCol] = *(const float4*)(W + (kc + bK) * FDIM + bCol);
        __syncthreads();

        #pragma unroll
        for (int k = 0; k < 8; k++) {
            float ar[8], bb[8];
            *(float4*)&ar[0] = *(const float4*)&As[k][ty * 8];
            *(float4*)&ar[4] = *(const float4*)&As[k][ty * 8 + 4];
            *(float4*)&bb[0] = *(const float4*)&Bs[k][tx * 8];
            *(float4*)&bb[4] = *(const float4*)&Bs[k][tx * 8 + 4];
            #pragma unroll
            for (int i = 0; i < 8; i++)
                #pragma unroll
                for (int j = 0; j < 8; j++)
                    c[i][j] = fmaf(ar[i], bb[j], c[i][j]);
        }
        __syncthreads();
    }

    float4 bs0 = *(const float4*)(bias + tx * 8);
    float4 bs1 = *(const float4*)(bias + tx * 8 + 4);
    #pragma unroll
    for (int i = 0; i < 8; i++) {
        int gr = row0 + ty * 8 + i;
        if (gr < NNODES) {
            float4 o0 = make_float4(c[i][0] + bs0.x, c[i][1] + bs0.y,
                                    c[i][2] + bs0.z, c[i][3] + bs0.w);
            float4 o1 = make_float4(c[i][4] + bs1.x, c[i][5] + bs1.y,
                                    c[i][6] + bs1.z, c[i][7] + bs1.w);
            *(float4*)(out + gr * FDIM + tx * 8)     = o0;
            *(float4*)(out + gr * FDIM + tx * 8 + 4) = o1;
        }
    }
}

// ---------------- GAT edge phase: 1 warp per dst node, online softmax ------
__global__ __launch_bounds__(256) void gat_kernel(
    const float* __restrict__ att, const float* __restrict__ bias,
    float* __restrict__ out_arg, int use_out_arg, int do_relu)
{
    const int warp = (blockIdx.x * blockDim.x + threadIdx.x) >> 5;
    if (warp >= NNODES) return;
    const int node = warp;
    const int lane = threadIdx.x & 31;

    float* out = use_out_arg ? out_arg : g_h;

    const float4* xl4 = (const float4*)g_xl;
    const float4  xr4 = ((const float4*)g_xr)[node * 32 + lane];
    const float4  at4 = ((const float4*)att)[lane];

    const int beg = g_rowptr[node];
    const int end = g_rowptr[node + 1];

    float  m = -__int_as_float(0x7f800000);   // -inf
    float  d = 0.f;
    float4 acc = make_float4(0.f, 0.f, 0.f, 0.f);

    for (int i = beg; i < end; i++) {
        int src = g_csrc[i];
        float4 v = xl4[src * 32 + lane];
        // leaky_relu(v + xr) elementwise, then dot with att
        float tx_ = v.x + xr4.x, ty_ = v.y + xr4.y;
        float tz_ = v.z + xr4.z, tw_ = v.w + xr4.w;
        tx_ = fmaxf(tx_, NEG_SLOPE * tx_);
        ty_ = fmaxf(ty_, NEG_SLOPE * ty_);
        tz_ = fmaxf(tz_, NEG_SLOPE * tz_);
        tw_ = fmaxf(tw_, NEG_SLOPE * tw_);
        float part = tx_ * at4.x;
        part = fmaf(ty_, at4.y, part);
        part = fmaf(tz_, at4.z, part);
        part = fmaf(tw_, at4.w, part);
        #pragma unroll
        for (int o = 16; o > 0; o >>= 1)
            part += __shfl_xor_sync(0xffffffffu, part, o);
        float s  = part;
        float mn = fmaxf(m, s);
        float scale = __expf(m - mn);   // 0 on first edge (m = -inf)
        float p     = __expf(s - mn);
        d = d * scale + p;
        acc.x = fmaf(p, v.x, acc.x * scale);
        acc.y = fmaf(p, v.y, acc.y * scale);
        acc.z = fmaf(p, v.z, acc.z * scale);
        acc.w = fmaf(p, v.w, acc.w * scale);
        m = mn;
    }

    float4 b4 = ((const float4*)bias)[lane];
    float4 o;
    if (d > 0.f) {
        float inv = 1.f / d;
        o = make_float4(fmaf(acc.x, inv, b4.x), fmaf(acc.y, inv, b4.y),
                        fmaf(acc.z, inv, b4.z), fmaf(acc.w, inv, b4.w));
    } else {
        o = b4;   // no in-edges: segment sums are 0 -> out = bias
    }
    if (do_relu) {
        o.x = fmaxf(o.x, 0.f); o.y = fmaxf(o.y, 0.f);
        o.z = fmaxf(o.z, 0.f); o.w = fmaxf(o.w, 0.f);
    }
    ((float4*)out)[node * 32 + lane] = o;
}

// ---------------- launch ----------------
extern "C" void kernel_launch(void* const* d_in, const int* in_sizes, int n_in,
                              void* d_out, int out_size) {
    const float* x    = (const float*)d_in[0];
    const int*   ei   = (const int*)  d_in[1];
    const float* Wl1  = (const float*)d_in[2];
    const float* bl1  = (const float*)d_in[3];
    const float* Wr1  = (const float*)d_in[4];
    const float* br1  = (const float*)d_in[5];
    const float* att1 = (const float*)d_in[6];
    const float* b1   = (const float*)d_in[7];
    const float* Wl2  = (const float*)d_in[8];
    const float* bl2  = (const float*)d_in[9];
    const float* Wr2  = (const float*)d_in[10];
    const float* br2  = (const float*)d_in[11];
    const float* att2 = (const float*)d_in[12];
    const float* b2   = (const float*)d_in[13];
    float* out = (float*)d_out;

    const int* src = ei;            // edge_idx[0]
    const int* dst = ei + NEDGES;   // edge_idx[1]

    // CSR build (edge_idx is an input; rebuilt every call for determinism)
    zero_deg_kernel<<<(NNODES + 255) / 256, 256>>>();
    count_kernel<<<(NEDGES + 255) / 256, 256>>>(dst);
    scan_kernel<<<1, 1024>>>();
    scatter_kernel<<<(NEDGES + 255) / 256, 256>>>(src, dst);

    dim3 ggrid((NNODES + 127) / 128, 2);
    const int gat_blocks = (NNODES * 32 + 255) / 256;

    // layer 1: x -> xl/xr -> h (relu)
    gemm_dual_kernel<<<ggrid, 256>>>(x, 0, Wl1, bl1, Wr1, br1);
    gat_kernel<<<gat_blocks, 256>>>(att1, b1, out, 0, 1);
    // layer 2: h -> xl/xr -> out
    gemm_dual_kernel<<<ggrid, 256>>>(x, 1, Wl2, bl2, Wr2, br2);
    gat_kernel<<<gat_blocks, 256>>>(att2, b2, out, 1, 0);
}

// round 3
// speedup vs baseline: 1.1501x; 1.1501x over previous
#include <cuda_runtime.h>
#include <cuda_bf16.h>
#include <cstdint>

#define NNODES 50000
#define NEDGES 800000
#define FDIM   128
#define NEG_SLOPE 0.2f
#define LDAB   272          // padded row stride in bytes (136 bf16 elems)

// ---------------- scratch (device globals: allocation-free) ----------------
__device__ float g_xl[NNODES * FDIM];
__device__ float g_xr[NNODES * FDIM];
__device__ float g_h [NNODES * FDIM];
__device__ int   g_deg[NNODES];
__device__ int   g_cursor[NNODES];
__device__ int   g_rowptr[NNODES + 1];
__device__ int   g_csrc[NEDGES];
// weight images: [layer][Wl_hi, Wl_lo, Wr_hi, Wr_lo], each [128][136] bf16
__device__ __align__(16) unsigned char g_wimg[2][4][128 * LDAB];

// ---------------- mma.sync helpers (plain sm_80+ PTX; no tcgen05) ----------
__device__ __forceinline__ uint32_t smem_u32(const void* p) {
    uint32_t a;
    asm("{ .reg .u64 t; cvta.to.shared.u64 t, %1; cvt.u32.u64 %0, t; }" : "=r"(a) : "l"(p));
    return a;
}
__device__ __forceinline__ void ldsm4(uint32_t* r, uint32_t a) {
    asm volatile("ldmatrix.sync.aligned.m8n8.x4.shared.b16 {%0,%1,%2,%3}, [%4];"
                 : "=r"(r[0]), "=r"(r[1]), "=r"(r[2]), "=r"(r[3]) : "r"(a));
}
__device__ __forceinline__ void ldsm4t(uint32_t* r, uint32_t a) {
    asm volatile("ldmatrix.sync.aligned.m8n8.x4.trans.shared.b16 {%0,%1,%2,%3}, [%4];"
                 : "=r"(r[0]), "=r"(r[1]), "=r"(r[2]), "=r"(r[3]) : "r"(a));
}
__device__ __forceinline__ void mma16816(float* c, const uint32_t* a, const uint32_t* b) {
    asm volatile(
        "mma.sync.aligned.m16n8k16.row.col.f32.bf16.bf16.f32 "
        "{%0,%1,%2,%3}, {%4,%5,%6,%7}, {%8,%9}, {%0,%1,%2,%3};"
        : "+f"(c[0]), "+f"(c[1]), "+f"(c[2]), "+f"(c[3])
        : "r"(a[0]), "r"(a[1]), "r"(a[2]), "r"(a[3]), "r"(b[0]), "r"(b[1]));
}

// ---------------- weight prep: W[k][n] fp32 -> (hi,lo) padded bf16 images --
__global__ void prep_w_kernel(const float* __restrict__ Wl1, const float* __restrict__ Wr1,
                              const float* __restrict__ Wl2, const float* __restrict__ Wr2) {
    int b = blockIdx.x;                 // 0:Wl1 1:Wr1 2:Wl2 3:Wr2
    const float* W = (b == 0) ? Wl1 : (b == 1) ? Wr1 : (b == 2) ? Wl2 : Wr2;
    int layer = b >> 1, side = b & 1;
    unsigned char* hi_img = g_wimg[layer][side * 2 + 0];
    unsigned char* lo_img = g_wimg[layer][side * 2 + 1];
    for (int i = threadIdx.x; i < FDIM * FDIM; i += blockDim.x) {
        int k = i >> 7, n = i & 127;
        float v = W[k * FDIM + n];
        __nv_bfloat16 h = __float2bfloat16_rn(v);
        __nv_bfloat16 l = __float2bfloat16_rn(v - __bfloat162float(h));
        uint32_t off = (uint32_t)k * LDAB + (uint32_t)n * 2;
        *(__nv_bfloat16*)(hi_img + off) = h;
        *(__nv_bfloat16*)(lo_img + off) = l;
    }
}

// ---------------- HMMA dual GEMM: g_xl = A@Wl+bl, g_xr = A@Wr+br ----------
// grid 391, block 512 (16 warps). Warp tile 32x64. bf16 hi/lo 3-pass split.
#define SM_AHI 0
#define SM_ALO (128 * LDAB)                 // 34816
#define SM_W   (2 * 128 * LDAB)             // 69632
#define SM_TOTAL (6 * 128 * LDAB)           // 208896 bytes

__global__ __launch_bounds__(512, 1) void gemm_mma_kernel(
    const float* __restrict__ Aarg, int use_h, int layer,
    const float* __restrict__ bl, const float* __restrict__ br)
{
    extern __shared__ unsigned char smem[];
    const float* A = use_h ? g_h : Aarg;
    const int tid  = threadIdx.x;
    const int row0 = blockIdx.x * 128;

    // copy the 4 weight images (136KB, L2-resident)
    {
        const int4* s = (const int4*)g_wimg[layer][0];
        int4* d = (int4*)(smem + SM_W);
        #pragma unroll 4
        for (int i = tid; i < 4 * 128 * LDAB / 16; i += 512) d[i] = s[i];
    }
    // load + split A tile into padded bf16 hi/lo
    for (int i = tid; i < FDIM * FDIM / 4; i += 512) {
        int e = i * 4;
        int row = e >> 7, col = e & 127;
        int gr = row0 + row;
        float4 v = (gr < NNODES) ? *(const float4*)(A + (size_t)gr * FDIM + col)
                                 : make_float4(0.f, 0.f, 0.f, 0.f);
        __nv_bfloat16 h0 = __float2bfloat16_rn(v.x), h1 = __float2bfloat16_rn(v.y);
        __nv_bfloat16 h2 = __float2bfloat16_rn(v.z), h3 = __float2bfloat16_rn(v.w);
        __nv_bfloat16 l0 = __float2bfloat16_rn(v.x - __bfloat162float(h0));
        __nv_bfloat16 l1 = __float2bfloat16_rn(v.y - __bfloat162float(h1));
        __nv_bfloat16 l2 = __float2bfloat16_rn(v.z - __bfloat162float(h2));
        __nv_bfloat16 l3 = __float2bfloat16_rn(v.w - __bfloat162float(h3));
        uint32_t off = (uint32_t)row * LDAB + (uint32_t)col * 2;
        __nv_bfloat162 p;
        p.x = h0; p.y = h1; *(__nv_bfloat162*)(smem + SM_AHI + off)     = p;
        p.x = h2; p.y = h3; *(__nv_bfloat162*)(smem + SM_AHI + off + 4) = p;
        p.x = l0; p.y = l1; *(__nv_bfloat162*)(smem + SM_ALO + off)     = p;
        p.x = l2; p.y = l3; *(__nv_bfloat162*)(smem + SM_ALO + off + 4) = p;
    }
    __syncthreads();

    const int lane = tid & 31, wid = tid >> 5;
    const int side = wid >> 3;              // 0 -> Wl/xl, 1 -> Wr/xr
    const int w    = wid & 7;
    const int m0   = (w & 3) * 32;
    const int n0   = (w >> 2) * 64;

    const uint32_t sbase = smem_u32(smem);
    const uint32_t lrow   = lane & 15;
    const uint32_t lcol16 = (lane >> 4) * 16;

    const uint32_t abase_hi = sbase + SM_AHI;
    const uint32_t abase_lo = sbase + SM_ALO;
    const uint32_t wbase_hi = sbase + SM_W + (uint32_t)side * 2u * (128 * LDAB);
    const uint32_t wbase_lo = wbase_hi + 128 * LDAB;

    float acc[2][8][4];
    #pragma unroll
    for (int i = 0; i < 2; i++)
        #pragma unroll
        for (int j = 0; j < 8; j++)
            #pragma unroll
            for (int q = 0; q < 4; q++) acc[i][j][q] = 0.f;

    #pragma unroll
    for (int pass = 0; pass < 3; pass++) {
        const uint32_t ab = (pass == 2) ? abase_lo : abase_hi;   // Ahi,Ahi,Alo
        const uint32_t wb = (pass == 1) ? wbase_lo : wbase_hi;   // Whi,Wlo,Whi
        const uint32_t a_lane = ab + (m0 + lrow) * LDAB + lcol16;
        const uint32_t b_lane = wb + lrow * LDAB + lcol16 + (uint32_t)n0 * 2;
        #pragma unroll
        for (int k0 = 0; k0 < FDIM; k0 += 16) {
            uint32_t a0[4], a1[4];
            ldsm4(a0, a_lane + k0 * 2);
            ldsm4(a1, a_lane + k0 * 2 + 16 * LDAB);
            const uint32_t bk = b_lane + (uint32_t)k0 * LDAB;
            #pragma unroll
            for (int p = 0; p < 4; p++) {
                uint32_t b[4];
                ldsm4t(b, bk + p * 32);
                mma16816(acc[0][2 * p],     a0, b + 0);
                mma16816(acc[0][2 * p + 1], a0, b + 2);
                mma16816(acc[1][2 * p],     a1, b + 0);
                mma16816(acc[1][2 * p + 1], a1, b + 2);
            }
        }
    }

    // epilogue: c0,c1 -> (row g, col 2t,2t+1); c2,c3 -> row g+8
    const float* bias = side ? br : bl;
    float* outp       = side ? g_xr : g_xl;
    const int g = lane >> 2, t = lane & 3;
    #pragma unroll
    for (int mt = 0; mt < 2; mt++) {
        #pragma unroll
        for (int half = 0; half < 2; half++) {
            int gr = row0 + m0 + mt * 16 + g + half * 8;
            if (gr < NNODES) {
                float* op = outp + (size_t)gr * FDIM;
                #pragma unroll
                for (int nt = 0; nt < 8; nt++) {
                    int col = n0 + nt * 8 + 2 * t;
                    float2 bv = *(const float2*)(bias + col);
                    float2 o;
                    o.x = acc[mt][nt][half * 2 + 0] + bv.x;
                    o.y = acc[mt][nt][half * 2 + 1] + bv.y;
                    *(float2*)(op + col) = o;
                }
            }
        }
    }
}

// ---------------- CSR build ----------------
__global__ void zero_deg_kernel() {
    int i = blockIdx.x * blockDim.x + threadIdx.x;
    if (i < NNODES) g_deg[i] = 0;
}
__global__ void count_kernel(const int* __restrict__ dst) {
    int e = blockIdx.x * blockDim.x + threadIdx.x;
    if (e < NEDGES) atomicAdd(&g_deg[dst[e]], 1);
}
// single-block scan, shfl-based: each thread handles 49 contiguous elements
__global__ __launch_bounds__(1024) void scan_kernel() {
    __shared__ int wsum[32];
    const int tid = threadIdx.x, lane = tid & 31, wid = tid >> 5;
    const int CH = 49;                 // 49*1024 >= 50000
    int base = tid * CH;
    int vals[CH];
    int s = 0;
    #pragma unroll
    for (int j = 0; j < CH; j++) {
        int i = base + j;
        vals[j] = (i < NNODES) ? g_deg[i] : 0;
        s += vals[j];
    }
    int inc = s;
    #pragma unroll
    for (int o = 1; o < 32; o <<= 1) {
        int t = __shfl_up_sync(0xffffffffu, inc, o);
        if (lane >= o) inc += t;
    }
    if (lane == 31) wsum[wid] = inc;
    __syncthreads();
    if (wid == 0) {
        int w = wsum[lane];
        #pragma unroll
        for (int o = 1; o < 32; o <<= 1) {
            int t = __shfl_up_sync(0xffffffffu, w, o);
            if (lane >= o) w += t;
        }
        wsum[lane] = w;
    }
    __syncthreads();
    int run = inc - s + (wid > 0 ? wsum[wid - 1] : 0);
    #pragma unroll
    for (int j = 0; j < CH; j++) {
        int i = base + j;
        if (i < NNODES) { g_rowptr[i] = run; g_cursor[i] = run; run += vals[j]; }
    }
    if (tid == 1023) g_rowptr[NNODES] = run;
}
__global__ void scatter_kernel(const int* __restrict__ src, const int* __restrict__ dst) {
    int e = blockIdx.x * blockDim.x + threadIdx.x;
    if (e < NEDGES) {
        int p = atomicAdd(&g_cursor[dst[e]], 1);
        g_csrc[p] = src[e];
    }
}

// ---------------- GAT edge phase: 1 warp per dst node, online softmax ------
__global__ __launch_bounds__(256) void gat_kernel(
    const float* __restrict__ att, const float* __restrict__ bias,
    float* __restrict__ out_arg, int use_out_arg, int do_relu)
{
    const int warp = (blockIdx.x * blockDim.x + threadIdx.x) >> 5;
    if (warp >= NNODES) return;
    const int node = warp;
    const int lane = threadIdx.x & 31;

    float* out = use_out_arg ? out_arg : g_h;

    const float4* xl4 = (const float4*)g_xl;
    const float4  xr4 = ((const float4*)g_xr)[node * 32 + lane];
    const float4  at4 = ((const float4*)att)[lane];

    const int beg = g_rowptr[node];
    const int end = g_rowptr[node + 1];

    float  m = -__int_as_float(0x7f800000);
    float  d = 0.f;
    float4 acc = make_float4(0.f, 0.f, 0.f, 0.f);

    for (int i = beg; i < end; i++) {
        int src = g_csrc[i];
        float4 v = xl4[src * 32 + lane];
        float tx_ = v.x + xr4.x, ty_ = v.y + xr4.y;
        float tz_ = v.z + xr4.z, tw_ = v.w + xr4.w;
        tx_ = fmaxf(tx_, NEG_SLOPE * tx_);
        ty_ = fmaxf(ty_, NEG_SLOPE * ty_);
        tz_ = fmaxf(tz_, NEG_SLOPE * tz_);
        tw_ = fmaxf(tw_, NEG_SLOPE * tw_);
        float part = tx_ * at4.x;
        part = fmaf(ty_, at4.y, part);
        part = fmaf(tz_, at4.z, part);
        part = fmaf(tw_, at4.w, part);
        #pragma unroll
        for (int o = 16; o > 0; o >>= 1)
            part += __shfl_xor_sync(0xffffffffu, part, o);
        float s  = part;
        float mn = fmaxf(m, s);
        float scale = __expf(m - mn);
        float p     = __expf(s - mn);
        d = d * scale + p;
        acc.x = fmaf(p, v.x, acc.x * scale);
        acc.y = fmaf(p, v.y, acc.y * scale);
        acc.z = fmaf(p, v.z, acc.z * scale);
        acc.w = fmaf(p, v.w, acc.w * scale);
        m = mn;
    }

    float4 b4 = ((const float4*)bias)[lane];
    float4 o;
    if (d > 0.f) {
        float inv = 1.f / d;
        o = make_float4(fmaf(acc.x, inv, b4.x), fmaf(acc.y, inv, b4.y),
                        fmaf(acc.z, inv, b4.z), fmaf(acc.w, inv, b4.w));
    } else {
        o = b4;
    }
    if (do_relu) {
        o.x = fmaxf(o.x, 0.f); o.y = fmaxf(o.y, 0.f);
        o.z = fmaxf(o.z, 0.f); o.w = fmaxf(o.w, 0.f);
    }
    ((float4*)out)[node * 32 + lane] = o;
}

// ---------------- launch ----------------
extern "C" void kernel_launch(void* const* d_in, const int* in_sizes, int n_in,
                              void* d_out, int out_size) {
    const float* x    = (const float*)d_in[0];
    const int*   ei   = (const int*)  d_in[1];
    const float* Wl1  = (const float*)d_in[2];
    const float* bl1  = (const float*)d_in[3];
    const float* Wr1  = (const float*)d_in[4];
    const float* br1  = (const float*)d_in[5];
    const float* att1 = (const float*)d_in[6];
    const float* b1   = (const float*)d_in[7];
    const float* Wl2  = (const float*)d_in[8];
    const float* bl2  = (const float*)d_in[9];
    const float* Wr2  = (const float*)d_in[10];
    const float* br2  = (const float*)d_in[11];
    const float* att2 = (const float*)d_in[12];
    const float* b2   = (const float*)d_in[13];
    float* out = (float*)d_out;

    const int* src = ei;
    const int* dst = ei + NEDGES;

    cudaFuncSetAttribute(gemm_mma_kernel,
                         cudaFuncAttributeMaxDynamicSharedMemorySize, SM_TOTAL);

    prep_w_kernel<<<4, 256>>>(Wl1, Wr1, Wl2, Wr2);
    zero_deg_kernel<<<(NNODES + 255) / 256, 256>>>();
    count_kernel<<<(NEDGES + 255) / 256, 256>>>(dst);
    scan_kernel<<<1, 1024>>>();
    scatter_kernel<<<(NEDGES + 255) / 256, 256>>>(src, dst);

    const int ggrid = (NNODES + 127) / 128;
    const int gat_blocks = (NNODES * 32 + 255) / 256;

    gemm_mma_kernel<<<ggrid, 512, SM_TOTAL>>>(x, 0, 0, bl1, br1);
    gat_kernel<<<gat_blocks, 256>>>(att1, b1, out, 0, 1);
    gemm_mma_kernel<<<ggrid, 512, SM_TOTAL>>>(x, 1, 1, bl2, br2);
    gat_kernel<<<gat_blocks, 256>>>(att2, b2, out, 1, 0);
}

// round 4
// speedup vs baseline: 1.2823x; 1.1149x over previous
#include <cuda_runtime.h>
#include <cuda_bf16.h>
#include <cstdint>

#define NNODES 50000
#define NEDGES 800000
#define FDIM   128
#define NEG_SLOPE 0.2f
#define LDAB   272          // padded row stride in bytes (136 bf16 elems)
#define SCAN_B 256
#define NBLK   ((NNODES + SCAN_B - 1) / SCAN_B)   // 196

// ---------------- scratch (device globals: allocation-free) ----------------
__device__ float g_xl[NNODES * FDIM];
__device__ float g_xr[NNODES * FDIM];
__device__ float g_h [NNODES * FDIM];
__device__ int   g_deg[NNODES];
__device__ int   g_cursor[NNODES];
__device__ int   g_rowptr[NNODES];
__device__ int   g_bsum[NBLK];
__device__ int   g_csrc[NEDGES];
// weight images: [layer][Wl_hi, Wl_lo, Wr_hi, Wr_lo], each [128][136] bf16
__device__ __align__(16) unsigned char g_wimg[2][4][128 * LDAB];

// ---------------- mma.sync helpers (plain sm_80+ PTX; no tcgen05) ----------
__device__ __forceinline__ uint32_t smem_u32(const void* p) {
    uint32_t a;
    asm("{ .reg .u64 t; cvta.to.shared.u64 t, %1; cvt.u32.u64 %0, t; }" : "=r"(a) : "l"(p));
    return a;
}
__device__ __forceinline__ void ldsm4(uint32_t* r, uint32_t a) {
    asm volatile("ldmatrix.sync.aligned.m8n8.x4.shared.b16 {%0,%1,%2,%3}, [%4];"
                 : "=r"(r[0]), "=r"(r[1]), "=r"(r[2]), "=r"(r[3]) : "r"(a));
}
__device__ __forceinline__ void ldsm4t(uint32_t* r, uint32_t a) {
    asm volatile("ldmatrix.sync.aligned.m8n8.x4.trans.shared.b16 {%0,%1,%2,%3}, [%4];"
                 : "=r"(r[0]), "=r"(r[1]), "=r"(r[2]), "=r"(r[3]) : "r"(a));
}
__device__ __forceinline__ void mma16816(float* c, const uint32_t* a, const uint32_t* b) {
    asm volatile(
        "mma.sync.aligned.m16n8k16.row.col.f32.bf16.bf16.f32 "
        "{%0,%1,%2,%3}, {%4,%5,%6,%7}, {%8,%9}, {%0,%1,%2,%3};"
        : "+f"(c[0]), "+f"(c[1]), "+f"(c[2]), "+f"(c[3])
        : "r"(a[0]), "r"(a[1]), "r"(a[2]), "r"(a[3]), "r"(b[0]), "r"(b[1]));
}

// ---------------- weight prep: W[k][n] fp32 -> (hi,lo) padded bf16 images --
__global__ void prep_w_kernel(const float* __restrict__ Wl1, const float* __restrict__ Wr1,
                              const float* __restrict__ Wl2, const float* __restrict__ Wr2) {
    int b = blockIdx.x;                 // 0:Wl1 1:Wr1 2:Wl2 3:Wr2
    const float* W = (b == 0) ? Wl1 : (b == 1) ? Wr1 : (b == 2) ? Wl2 : Wr2;
    int layer = b >> 1, side = b & 1;
    unsigned char* hi_img = g_wimg[layer][side * 2 + 0];
    unsigned char* lo_img = g_wimg[layer][side * 2 + 1];
    for (int i = threadIdx.x; i < FDIM * FDIM; i += blockDim.x) {
        int k = i >> 7, n = i & 127;
        float v = W[k * FDIM + n];
        __nv_bfloat16 h = __float2bfloat16_rn(v);
        __nv_bfloat16 l = __float2bfloat16_rn(v - __bfloat162float(h));
        uint32_t off = (uint32_t)k * LDAB + (uint32_t)n * 2;
        *(__nv_bfloat16*)(hi_img + off) = h;
        *(__nv_bfloat16*)(lo_img + off) = l;
    }
}

// ---------------- CSR build ----------------
__global__ void zero_deg_kernel() {
    int i = blockIdx.x * blockDim.x + threadIdx.x;
    if (i < NNODES) g_deg[i] = 0;
}
__global__ void count_kernel(const int* __restrict__ dst) {
    int e = blockIdx.x * blockDim.x + threadIdx.x;
    if (e < NEDGES) atomicAdd(&g_deg[dst[e]], 1);
}
// scan A: per-block degree sums
__global__ __launch_bounds__(SCAN_B) void bsum_kernel() {
    __shared__ int ws[SCAN_B / 32];
    int i = blockIdx.x * SCAN_B + threadIdx.x;
    int v = (i < NNODES) ? g_deg[i] : 0;
    int s = v;
    #pragma unroll
    for (int o = 16; o > 0; o >>= 1) s += __shfl_xor_sync(0xffffffffu, s, o);
    int lane = threadIdx.x & 31, wid = threadIdx.x >> 5;
    if (lane == 0) ws[wid] = s;
    __syncthreads();
    if (threadIdx.x == 0) {
        int t = 0;
        #pragma unroll
        for (int j = 0; j < SCAN_B / 32; j++) t += ws[j];
        g_bsum[blockIdx.x] = t;
    }
}
// scan B: block offset = sum of previous block sums; local exclusive scan
__global__ __launch_bounds__(SCAN_B) void bscan_kernel() {
    __shared__ int ws[SCAN_B / 32];
    __shared__ int s_off;
    const int tid = threadIdx.x, lane = tid & 31, wid = tid >> 5;
    // offset: reduce g_bsum[0..blockIdx.x)
    int p = (tid < blockIdx.x) ? g_bsum[tid] : 0;   // NBLK=196 < 256
    int ps = p;
    #pragma unroll
    for (int o = 16; o > 0; o >>= 1) ps += __shfl_xor_sync(0xffffffffu, ps, o);
    if (lane == 0) ws[wid] = ps;
    __syncthreads();
    if (tid == 0) {
        int t = 0;
        #pragma unroll
        for (int j = 0; j < SCAN_B / 32; j++) t += ws[j];
        s_off = t;
    }
    __syncthreads();
    // local exclusive scan of 256 degrees
    int i = blockIdx.x * SCAN_B + tid;
    int v = (i < NNODES) ? g_deg[i] : 0;
    int inc = v;
    #pragma unroll
    for (int o = 1; o < 32; o <<= 1) {
        int t = __shfl_up_sync(0xffffffffu, inc, o);
        if (lane >= o) inc += t;
    }
    __syncthreads();
    if (lane == 31) ws[wid] = inc;
    __syncthreads();
    int wo = 0;
    #pragma unroll
    for (int j = 0; j < SCAN_B / 32; j++) wo += (j < wid) ? ws[j] : 0;
    if (i < NNODES) {
        int excl = s_off + wo + inc - v;
        g_rowptr[i] = excl;
        g_cursor[i] = excl;
    }
}
__global__ void scatter_kernel(const int* __restrict__ src, const int* __restrict__ dst) {
    int e = blockIdx.x * blockDim.x + threadIdx.x;
    if (e < NEDGES) {
        int p = atomicAdd(&g_cursor[dst[e]], 1);
        g_csrc[p] = src[e];
    }
}

// ---------------- HMMA dual GEMM: g_xl = A@Wl+bl, g_xr = A@Wr+br ----------
// grid 391, block 512 (16 warps). Warp tile 32x64. bf16 hi/lo 3-pass split.
#define SM_AHI 0
#define SM_ALO (128 * LDAB)                 // 34816
#define SM_W   (2 * 128 * LDAB)             // 69632
#define SM_TOTAL (6 * 128 * LDAB)           // 208896 bytes

__global__ __launch_bounds__(512, 1) void gemm_mma_kernel(
    const float* __restrict__ Aarg, int use_h, int layer,
    const float* __restrict__ bl, const float* __restrict__ br)
{
    extern __shared__ unsigned char smem[];
    const float* A = use_h ? g_h : Aarg;
    const int tid  = threadIdx.x;
    const int row0 = blockIdx.x * 128;

    // copy the 4 weight images (136KB, L2-resident)
    {
        const int4* s = (const int4*)g_wimg[layer][0];
        int4* d = (int4*)(smem + SM_W);
        #pragma unroll 4
        for (int i = tid; i < 4 * 128 * LDAB / 16; i += 512) d[i] = s[i];
    }
    // load + split A tile into padded bf16 hi/lo
    for (int i = tid; i < FDIM * FDIM / 4; i += 512) {
        int e = i * 4;
        int row = e >> 7, col = e & 127;
        int gr = row0 + row;
        float4 v = (gr < NNODES) ? *(const float4*)(A + (size_t)gr * FDIM + col)
                                 : make_float4(0.f, 0.f, 0.f, 0.f);
        __nv_bfloat16 h0 = __float2bfloat16_rn(v.x), h1 = __float2bfloat16_rn(v.y);
        __nv_bfloat16 h2 = __float2bfloat16_rn(v.z), h3 = __float2bfloat16_rn(v.w);
        __nv_bfloat16 l0 = __float2bfloat16_rn(v.x - __bfloat162float(h0));
        __nv_bfloat16 l1 = __float2bfloat16_rn(v.y - __bfloat162float(h1));
        __nv_bfloat16 l2 = __float2bfloat16_rn(v.z - __bfloat162float(h2));
        __nv_bfloat16 l3 = __float2bfloat16_rn(v.w - __bfloat162float(h3));
        uint32_t off = (uint32_t)row * LDAB + (uint32_t)col * 2;
        __nv_bfloat162 p;
        p.x = h0; p.y = h1; *(__nv_bfloat162*)(smem + SM_AHI + off)     = p;
        p.x = h2; p.y = h3; *(__nv_bfloat162*)(smem + SM_AHI + off + 4) = p;
        p.x = l0; p.y = l1; *(__nv_bfloat162*)(smem + SM_ALO + off)     = p;
        p.x = l2; p.y = l3; *(__nv_bfloat162*)(smem + SM_ALO + off + 4) = p;
    }
    __syncthreads();

    const int lane = tid & 31, wid = tid >> 5;
    const int side = wid >> 3;              // 0 -> Wl/xl, 1 -> Wr/xr
    const int w    = wid & 7;
    const int m0   = (w & 3) * 32;
    const int n0   = (w >> 2) * 64;

    const uint32_t sbase = smem_u32(smem);
    const uint32_t lrow   = lane & 15;
    const uint32_t lcol16 = (lane >> 4) * 16;

    const uint32_t abase_hi = sbase + SM_AHI;
    const uint32_t abase_lo = sbase + SM_ALO;
    const uint32_t wbase_hi = sbase + SM_W + (uint32_t)side * 2u * (128 * LDAB);
    const uint32_t wbase_lo = wbase_hi + 128 * LDAB;

    float acc[2][8][4];
    #pragma unroll
    for (int i = 0; i < 2; i++)
        #pragma unroll
        for (int j = 0; j < 8; j++)
            #pragma unroll
            for (int q = 0; q < 4; q++) acc[i][j][q] = 0.f;

    #pragma unroll
    for (int pass = 0; pass < 3; pass++) {
        const uint32_t ab = (pass == 2) ? abase_lo : abase_hi;   // Ahi,Ahi,Alo
        const uint32_t wb = (pass == 1) ? wbase_lo : wbase_hi;   // Whi,Wlo,Whi
        const uint32_t a_lane = ab + (m0 + lrow) * LDAB + lcol16;
        const uint32_t b_lane = wb + lrow * LDAB + lcol16 + (uint32_t)n0 * 2;
        #pragma unroll
        for (int k0 = 0; k0 < FDIM; k0 += 16) {
            uint32_t a0[4], a1[4];
            ldsm4(a0, a_lane + k0 * 2);
            ldsm4(a1, a_lane + k0 * 2 + 16 * LDAB);
            const uint32_t bk = b_lane + (uint32_t)k0 * LDAB;
            #pragma unroll
            for (int p = 0; p < 4; p++) {
                uint32_t b[4];
                ldsm4t(b, bk + p * 32);
                mma16816(acc[0][2 * p],     a0, b + 0);
                mma16816(acc[0][2 * p + 1], a0, b + 2);
                mma16816(acc[1][2 * p],     a1, b + 0);
                mma16816(acc[1][2 * p + 1], a1, b + 2);
            }
        }
    }

    // epilogue: c0,c1 -> (row g, col 2t,2t+1); c2,c3 -> row g+8
    const float* bias = side ? br : bl;
    float* outp       = side ? g_xr : g_xl;
    const int g = lane >> 2, t = lane & 3;
    #pragma unroll
    for (int mt = 0; mt < 2; mt++) {
        #pragma unroll
        for (int half = 0; half < 2; half++) {
            int gr = row0 + m0 + mt * 16 + g + half * 8;
            if (gr < NNODES) {
                float* op = outp + (size_t)gr * FDIM;
                #pragma unroll
                for (int nt = 0; nt < 8; nt++) {
                    int col = n0 + nt * 8 + 2 * t;
                    float2 bv = *(const float2*)(bias + col);
                    float2 o;
                    o.x = acc[mt][nt][half * 2 + 0] + bv.x;
                    o.y = acc[mt][nt][half * 2 + 1] + bv.y;
                    *(float2*)(op + col) = o;
                }
            }
        }
    }
}

// ---------------- GAT edge phase: 1 warp per dst node, online softmax ------
__global__ __launch_bounds__(256) void gat_kernel(
    const float* __restrict__ att, const float* __restrict__ bias,
    float* __restrict__ out_arg, int use_out_arg, int do_relu)
{
    const int warp = (blockIdx.x * blockDim.x + threadIdx.x) >> 5;
    if (warp >= NNODES) return;
    const int node = warp;
    const int lane = threadIdx.x & 31;

    float* out = use_out_arg ? out_arg : g_h;

    const float4* xl4 = (const float4*)g_xl;
    const float4  xr4 = ((const float4*)g_xr)[node * 32 + lane];
    const float4  at4 = ((const float4*)att)[lane];

    const int beg = g_rowptr[node];
    const int end = beg + g_deg[node];

    float  m = -__int_as_float(0x7f800000);
    float  d = 0.f;
    float4 acc = make_float4(0.f, 0.f, 0.f, 0.f);

    for (int i = beg; i < end; i++) {
        int src = g_csrc[i];
        float4 v = xl4[src * 32 + lane];
        float tx_ = v.x + xr4.x, ty_ = v.y + xr4.y;
        float tz_ = v.z + xr4.z, tw_ = v.w + xr4.w;
        tx_ = fmaxf(tx_, NEG_SLOPE * tx_);
        ty_ = fmaxf(ty_, NEG_SLOPE * ty_);
        tz_ = fmaxf(tz_, NEG_SLOPE * tz_);
        tw_ = fmaxf(tw_, NEG_SLOPE * tw_);
        float part = tx_ * at4.x;
        part = fmaf(ty_, at4.y, part);
        part = fmaf(tz_, at4.z, part);
        part = fmaf(tw_, at4.w, part);
        #pragma unroll
        for (int o = 16; o > 0; o >>= 1)
            part += __shfl_xor_sync(0xffffffffu, part, o);
        float s  = part;
        float mn = fmaxf(m, s);
        float scale = __expf(m - mn);
        float p     = __expf(s - mn);
        d = d * scale + p;
        acc.x = fmaf(p, v.x, acc.x * scale);
        acc.y = fmaf(p, v.y, acc.y * scale);
        acc.z = fmaf(p, v.z, acc.z * scale);
        acc.w = fmaf(p, v.w, acc.w * scale);
        m = mn;
    }

    float4 b4 = ((const float4*)bias)[lane];
    float4 o;
    if (d > 0.f) {
        float inv = 1.f / d;
        o = make_float4(fmaf(acc.x, inv, b4.x), fmaf(acc.y, inv, b4.y),
                        fmaf(acc.z, inv, b4.z), fmaf(acc.w, inv, b4.w));
    } else {
        o = b4;
    }
    if (do_relu) {
        o.x = fmaxf(o.x, 0.f); o.y = fmaxf(o.y, 0.f);
        o.z = fmaxf(o.z, 0.f); o.w = fmaxf(o.w, 0.f);
    }
    ((float4*)out)[node * 32 + lane] = o;
}

// ---------------- launch ----------------
extern "C" void kernel_launch(void* const* d_in, const int* in_sizes, int n_in,
                              void* d_out, int out_size) {
    const float* x    = (const float*)d_in[0];
    const int*   ei   = (const int*)  d_in[1];
    const float* Wl1  = (const float*)d_in[2];
    const float* bl1  = (const float*)d_in[3];
    const float* Wr1  = (const float*)d_in[4];
    const float* br1  = (const float*)d_in[5];
    const float* att1 = (const float*)d_in[6];
    const float* b1   = (const float*)d_in[7];
    const float* Wl2  = (const float*)d_in[8];
    const float* bl2  = (const float*)d_in[9];
    const float* Wr2  = (const float*)d_in[10];
    const float* br2  = (const float*)d_in[11];
    const float* att2 = (const float*)d_in[12];
    const float* b2   = (const float*)d_in[13];
    float* out = (float*)d_out;

    const int* src = ei;
    const int* dst = ei + NEDGES;

    cudaFuncSetAttribute(gemm_mma_kernel,
                         cudaFuncAttributeMaxDynamicSharedMemorySize, SM_TOTAL);

    const int ggrid = (NNODES + 127) / 128;
    const int gat_blocks = (NNODES * 32 + 255) / 256;

    // order chosen so ncu (-s 5) captures gemm_mma_kernel (launch #5)
    prep_w_kernel<<<4, 256>>>(Wl1, Wr1, Wl2, Wr2);              // 0
    zero_deg_kernel<<<(NNODES + 255) / 256, 256>>>();           // 1
    count_kernel<<<(NEDGES + 255) / 256, 256>>>(dst);           // 2
    bsum_kernel<<<NBLK, SCAN_B>>>();                            // 3
    bscan_kernel<<<NBLK, SCAN_B>>>();                           // 4
    gemm_mma_kernel<<<ggrid, 512, SM_TOTAL>>>(x, 0, 0, bl1, br1);   // 5 (profiled)
    scatter_kernel<<<(NEDGES + 255) / 256, 256>>>(src, dst);    // 6
    gat_kernel<<<gat_blocks, 256>>>(att1, b1, out, 0, 1);       // 7
    gemm_mma_kernel<<<ggrid, 512, SM_TOTAL>>>(x, 1, 1, bl2, br2);   // 8
    gat_kernel<<<gat_blocks, 256>>>(att2, b2, out, 1, 0);       // 9
}

// round 5
// speedup vs baseline: 1.5682x; 1.2230x over previous
#include <cuda_runtime.h>
#include <cuda_bf16.h>
#include <cstdint>

#define NNODES 50000
#define NEDGES 800000
#define FDIM   128
#define NEG_SLOPE 0.2f
#define LDAB   272          // padded row stride in bytes (136 bf16 elems)
#define SCAN_B 256
#define NBLK   ((NNODES + SCAN_B - 1) / SCAN_B)   // 196

// ---------------- scratch (device globals: allocation-free) ----------------
__device__ float g_xl[NNODES * FDIM];
__device__ float g_xr[NNODES * FDIM];
__device__ float g_h [NNODES * FDIM];
__device__ int   g_deg[NNODES];
__device__ int   g_cursor[NNODES];
__device__ int   g_rowptr[NNODES];
__device__ int   g_bsum[NBLK];
__device__ int   g_csrc[NEDGES];
// weight images: [layer][Wl_hi, Wl_lo, Wr_hi, Wr_lo], each [128][136] bf16
__device__ __align__(16) unsigned char g_wimg[2][4][128 * LDAB];

// ---------------- mma.sync helpers (plain sm_80+ PTX; no tcgen05) ----------
__device__ __forceinline__ uint32_t smem_u32(const void* p) {
    uint32_t a;
    asm("{ .reg .u64 t; cvta.to.shared.u64 t, %1; cvt.u32.u64 %0, t; }" : "=r"(a) : "l"(p));
    return a;
}
__device__ __forceinline__ void ldsm4(uint32_t* r, uint32_t a) {
    asm volatile("ldmatrix.sync.aligned.m8n8.x4.shared.b16 {%0,%1,%2,%3}, [%4];"
                 : "=r"(r[0]), "=r"(r[1]), "=r"(r[2]), "=r"(r[3]) : "r"(a));
}
__device__ __forceinline__ void ldsm4t(uint32_t* r, uint32_t a) {
    asm volatile("ldmatrix.sync.aligned.m8n8.x4.trans.shared.b16 {%0,%1,%2,%3}, [%4];"
                 : "=r"(r[0]), "=r"(r[1]), "=r"(r[2]), "=r"(r[3]) : "r"(a));
}
__device__ __forceinline__ void mma16816(float* c, const uint32_t* a, const uint32_t* b) {
    asm volatile(
        "mma.sync.aligned.m16n8k16.row.col.f32.bf16.bf16.f32 "
        "{%0,%1,%2,%3}, {%4,%5,%6,%7}, {%8,%9}, {%0,%1,%2,%3};"
        : "+f"(c[0]), "+f"(c[1]), "+f"(c[2]), "+f"(c[3])
        : "r"(a[0]), "r"(a[1]), "r"(a[2]), "r"(a[3]), "r"(b[0]), "r"(b[1]));
}

// ---------------- weight prep: W[k][n] fp32 -> (hi,lo) padded bf16 images --
__global__ void prep_w_kernel(const float* __restrict__ Wl1, const float* __restrict__ Wr1,
                              const float* __restrict__ Wl2, const float* __restrict__ Wr2) {
    int b = blockIdx.x;                 // 0:Wl1 1:Wr1 2:Wl2 3:Wr2
    const float* W = (b == 0) ? Wl1 : (b == 1) ? Wr1 : (b == 2) ? Wl2 : Wr2;
    int layer = b >> 1, side = b & 1;
    unsigned char* hi_img = g_wimg[layer][side * 2 + 0];
    unsigned char* lo_img = g_wimg[layer][side * 2 + 1];
    for (int i = threadIdx.x; i < FDIM * FDIM; i += blockDim.x) {
        int k = i >> 7, n = i & 127;
        float v = W[k * FDIM + n];
        __nv_bfloat16 h = __float2bfloat16_rn(v);
        __nv_bfloat16 l = __float2bfloat16_rn(v - __bfloat162float(h));
        uint32_t off = (uint32_t)k * LDAB + (uint32_t)n * 2;
        *(__nv_bfloat16*)(hi_img + off) = h;
        *(__nv_bfloat16*)(lo_img + off) = l;
    }
}

// ---------------- CSR build ----------------
__global__ void count_kernel(const int* __restrict__ dst) {
    int e = blockIdx.x * blockDim.x + threadIdx.x;
    if (e < NEDGES) atomicAdd(&g_deg[dst[e]], 1);
}
__global__ __launch_bounds__(SCAN_B) void bsum_kernel() {
    __shared__ int ws[SCAN_B / 32];
    int i = blockIdx.x * SCAN_B + threadIdx.x;
    int v = (i < NNODES) ? g_deg[i] : 0;
    int s = v;
    #pragma unroll
    for (int o = 16; o > 0; o >>= 1) s += __shfl_xor_sync(0xffffffffu, s, o);
    int lane = threadIdx.x & 31, wid = threadIdx.x >> 5;
    if (lane == 0) ws[wid] = s;
    __syncthreads();
    if (threadIdx.x == 0) {
        int t = 0;
        #pragma unroll
        for (int j = 0; j < SCAN_B / 32; j++) t += ws[j];
        g_bsum[blockIdx.x] = t;
    }
}
__global__ __launch_bounds__(SCAN_B) void bscan_kernel() {
    __shared__ int ws[SCAN_B / 32];
    __shared__ int s_off;
    const int tid = threadIdx.x, lane = tid & 31, wid = tid >> 5;
    int p = (tid < blockIdx.x) ? g_bsum[tid] : 0;   // NBLK=196 < 256
    int ps = p;
    #pragma unroll
    for (int o = 16; o > 0; o >>= 1) ps += __shfl_xor_sync(0xffffffffu, ps, o);
    if (lane == 0) ws[wid] = ps;
    __syncthreads();
    if (tid == 0) {
        int t = 0;
        #pragma unroll
        for (int j = 0; j < SCAN_B / 32; j++) t += ws[j];
        s_off = t;
    }
    __syncthreads();
    int i = blockIdx.x * SCAN_B + tid;
    int v = (i < NNODES) ? g_deg[i] : 0;
    int inc = v;
    #pragma unroll
    for (int o = 1; o < 32; o <<= 1) {
        int t = __shfl_up_sync(0xffffffffu, inc, o);
        if (lane >= o) inc += t;
    }
    __syncthreads();
    if (lane == 31) ws[wid] = inc;
    __syncthreads();
    int wo = 0;
    #pragma unroll
    for (int j = 0; j < SCAN_B / 32; j++) wo += (j < wid) ? ws[j] : 0;
    if (i < NNODES) {
        int excl = s_off + wo + inc - v;
        g_rowptr[i] = excl;
        g_cursor[i] = excl;
    }
}
__global__ void scatter_kernel(const int* __restrict__ src, const int* __restrict__ dst) {
    int e = blockIdx.x * blockDim.x + threadIdx.x;
    if (e < NEDGES) {
        int p = atomicAdd(&g_cursor[dst[e]], 1);
        g_csrc[p] = src[e];
    }
}

// ---------------- HMMA dual GEMM: g_xl = A@Wl+bl, g_xr = A@Wr+br ----------
#define SM_AHI 0
#define SM_ALO (128 * LDAB)                 // 34816
#define SM_W   (2 * 128 * LDAB)             // 69632
#define SM_TOTAL (6 * 128 * LDAB)           // 208896 bytes

__global__ __launch_bounds__(512, 1) void gemm_mma_kernel(
    const float* __restrict__ Aarg, int use_h, int layer,
    const float* __restrict__ bl, const float* __restrict__ br)
{
    extern __shared__ unsigned char smem[];
    const float* A = use_h ? g_h : Aarg;
    const int tid  = threadIdx.x;
    const int row0 = blockIdx.x * 128;

    {
        const int4* s = (const int4*)g_wimg[layer][0];
        int4* d = (int4*)(smem + SM_W);
        #pragma unroll 4
        for (int i = tid; i < 4 * 128 * LDAB / 16; i += 512) d[i] = s[i];
    }
    for (int i = tid; i < FDIM * FDIM / 4; i += 512) {
        int e = i * 4;
        int row = e >> 7, col = e & 127;
        int gr = row0 + row;
        float4 v = (gr < NNODES) ? *(const float4*)(A + (size_t)gr * FDIM + col)
                                 : make_float4(0.f, 0.f, 0.f, 0.f);
        __nv_bfloat16 h0 = __float2bfloat16_rn(v.x), h1 = __float2bfloat16_rn(v.y);
        __nv_bfloat16 h2 = __float2bfloat16_rn(v.z), h3 = __float2bfloat16_rn(v.w);
        __nv_bfloat16 l0 = __float2bfloat16_rn(v.x - __bfloat162float(h0));
        __nv_bfloat16 l1 = __float2bfloat16_rn(v.y - __bfloat162float(h1));
        __nv_bfloat16 l2 = __float2bfloat16_rn(v.z - __bfloat162float(h2));
        __nv_bfloat16 l3 = __float2bfloat16_rn(v.w - __bfloat162float(h3));
        uint32_t off = (uint32_t)row * LDAB + (uint32_t)col * 2;
        __nv_bfloat162 p;
        p.x = h0; p.y = h1; *(__nv_bfloat162*)(smem + SM_AHI + off)     = p;
        p.x = h2; p.y = h3; *(__nv_bfloat162*)(smem + SM_AHI + off + 4) = p;
        p.x = l0; p.y = l1; *(__nv_bfloat162*)(smem + SM_ALO + off)     = p;
        p.x = l2; p.y = l3; *(__nv_bfloat162*)(smem + SM_ALO + off + 4) = p;
    }
    __syncthreads();

    const int lane = tid & 31, wid = tid >> 5;
    const int side = wid >> 3;
    const int w    = wid & 7;
    const int m0   = (w & 3) * 32;
    const int n0   = (w >> 2) * 64;

    const uint32_t sbase = smem_u32(smem);
    const uint32_t lrow   = lane & 15;
    const uint32_t lcol16 = (lane >> 4) * 16;

    const uint32_t abase_hi = sbase + SM_AHI;
    const uint32_t abase_lo = sbase + SM_ALO;
    const uint32_t wbase_hi = sbase + SM_W + (uint32_t)side * 2u * (128 * LDAB);
    const uint32_t wbase_lo = wbase_hi + 128 * LDAB;

    float acc[2][8][4];
    #pragma unroll
    for (int i = 0; i < 2; i++)
        #pragma unroll
        for (int j = 0; j < 8; j++)
            #pragma unroll
            for (int q = 0; q < 4; q++) acc[i][j][q] = 0.f;

    #pragma unroll
    for (int pass = 0; pass < 3; pass++) {
        const uint32_t ab = (pass == 2) ? abase_lo : abase_hi;   // Ahi,Ahi,Alo
        const uint32_t wb = (pass == 1) ? wbase_lo : wbase_hi;   // Whi,Wlo,Whi
        const uint32_t a_lane = ab + (m0 + lrow) * LDAB + lcol16;
        const uint32_t b_lane = wb + lrow * LDAB + lcol16 + (uint32_t)n0 * 2;
        #pragma unroll
        for (int k0 = 0; k0 < FDIM; k0 += 16) {
            uint32_t a0[4], a1[4];
            ldsm4(a0, a_lane + k0 * 2);
            ldsm4(a1, a_lane + k0 * 2 + 16 * LDAB);
            const uint32_t bk = b_lane + (uint32_t)k0 * LDAB;
            #pragma unroll
            for (int p = 0; p < 4; p++) {
                uint32_t b[4];
                ldsm4t(b, bk + p * 32);
                mma16816(acc[0][2 * p],     a0, b + 0);
                mma16816(acc[0][2 * p + 1], a0, b + 2);
                mma16816(acc[1][2 * p],     a1, b + 0);
                mma16816(acc[1][2 * p + 1], a1, b + 2);
            }
        }
    }

    const float* bias = side ? br : bl;
    float* outp       = side ? g_xr : g_xl;
    const int g = lane >> 2, t = lane & 3;
    #pragma unroll
    for (int mt = 0; mt < 2; mt++) {
        #pragma unroll
        for (int half = 0; half < 2; half++) {
            int gr = row0 + m0 + mt * 16 + g + half * 8;
            if (gr < NNODES) {
                float* op = outp + (size_t)gr * FDIM;
                #pragma unroll
                for (int nt = 0; nt < 8; nt++) {
                    int col = n0 + nt * 8 + 2 * t;
                    float2 bv = *(const float2*)(bias + col);
                    float2 o;
                    o.x = acc[mt][nt][half * 2 + 0] + bv.x;
                    o.y = acc[mt][nt][half * 2 + 1] + bv.y;
                    *(float2*)(op + col) = o;
                }
            }
        }
    }
}

// ---------------- GAT edge phase: 1 warp/node, 2-edge batched softmax ------
__global__ __launch_bounds__(256) void gat_kernel(
    const float* __restrict__ att, const float* __restrict__ bias,
    float* __restrict__ out_arg, int use_out_arg, int do_relu)
{
    const int warp = (blockIdx.x * blockDim.x + threadIdx.x) >> 5;
    if (warp >= NNODES) return;
    const int node = warp;
    const int lane = threadIdx.x & 31;

    float* out = use_out_arg ? out_arg : g_h;

    const float4* xl4 = (const float4*)g_xl;
    const float4  xr4 = ((const float4*)g_xr)[node * 32 + lane];
    const float4  at4 = ((const float4*)att)[lane];

    const int beg = g_rowptr[node];
    const int end = beg + g_deg[node];

    float  m = -__int_as_float(0x7f800000);
    float  d = 0.f;
    float4 acc = make_float4(0.f, 0.f, 0.f, 0.f);

    int i = beg;
    for (; i + 2 <= end; i += 2) {
        int s0 = g_csrc[i], s1 = g_csrc[i + 1];
        float4 v0 = xl4[s0 * 32 + lane];
        float4 v1 = xl4[s1 * 32 + lane];
        float a0x = v0.x + xr4.x, a0y = v0.y + xr4.y, a0z = v0.z + xr4.z, a0w = v0.w + xr4.w;
        float a1x = v1.x + xr4.x, a1y = v1.y + xr4.y, a1z = v1.z + xr4.z, a1w = v1.w + xr4.w;
        a0x = fmaxf(a0x, NEG_SLOPE * a0x); a0y = fmaxf(a0y, NEG_SLOPE * a0y);
        a0z = fmaxf(a0z, NEG_SLOPE * a0z); a0w = fmaxf(a0w, NEG_SLOPE * a0w);
        a1x = fmaxf(a1x, NEG_SLOPE * a1x); a1y = fmaxf(a1y, NEG_SLOPE * a1y);
        a1z = fmaxf(a1z, NEG_SLOPE * a1z); a1w = fmaxf(a1w, NEG_SLOPE * a1w);
        float p0 = a0x * at4.x; p0 = fmaf(a0y, at4.y, p0);
        p0 = fmaf(a0z, at4.z, p0); p0 = fmaf(a0w, at4.w, p0);
        float p1 = a1x * at4.x; p1 = fmaf(a1y, at4.y, p1);
        p1 = fmaf(a1z, at4.z, p1); p1 = fmaf(a1w, at4.w, p1);
        #pragma unroll
        for (int o = 16; o > 0; o >>= 1) {
            p0 += __shfl_xor_sync(0xffffffffu, p0, o);
            p1 += __shfl_xor_sync(0xffffffffu, p1, o);
        }
        float mn = fmaxf(m, fmaxf(p0, p1));
        float scale = __expf(m - mn);
        float e0 = __expf(p0 - mn);
        float e1 = __expf(p1 - mn);
        d = d * scale + e0 + e1;
        acc.x = fmaf(e1, v1.x, fmaf(e0, v0.x, acc.x * scale));
        acc.y = fmaf(e1, v1.y, fmaf(e0, v0.y, acc.y * scale));
        acc.z = fmaf(e1, v1.z, fmaf(e0, v0.z, acc.z * scale));
        acc.w = fmaf(e1, v1.w, fmaf(e0, v0.w, acc.w * scale));
        m = mn;
    }
    if (i < end) {
        int s0 = g_csrc[i];
        float4 v0 = xl4[s0 * 32 + lane];
        float a0x = v0.x + xr4.x, a0y = v0.y + xr4.y, a0z = v0.z + xr4.z, a0w = v0.w + xr4.w;
        a0x = fmaxf(a0x, NEG_SLOPE * a0x); a0y = fmaxf(a0y, NEG_SLOPE * a0y);
        a0z = fmaxf(a0z, NEG_SLOPE * a0z); a0w = fmaxf(a0w, NEG_SLOPE * a0w);
        float p0 = a0x * at4.x; p0 = fmaf(a0y, at4.y, p0);
        p0 = fmaf(a0z, at4.z, p0); p0 = fmaf(a0w, at4.w, p0);
        #pragma unroll
        for (int o = 16; o > 0; o >>= 1)
            p0 += __shfl_xor_sync(0xffffffffu, p0, o);
        float mn = fmaxf(m, p0);
        float scale = __expf(m - mn);
        float e0 = __expf(p0 - mn);
        d = d * scale + e0;
        acc.x = fmaf(e0, v0.x, acc.x * scale);
        acc.y = fmaf(e0, v0.y, acc.y * scale);
        acc.z = fmaf(e0, v0.z, acc.z * scale);
        acc.w = fmaf(e0, v0.w, acc.w * scale);
    }

    float4 b4 = ((const float4*)bias)[lane];
    float4 o;
    if (d > 0.f) {
        float inv = 1.f / d;
        o = make_float4(fmaf(acc.x, inv, b4.x), fmaf(acc.y, inv, b4.y),
                        fmaf(acc.z, inv, b4.z), fmaf(acc.w, inv, b4.w));
    } else {
        o = b4;
    }
    if (do_relu) {
        o.x = fmaxf(o.x, 0.f); o.y = fmaxf(o.y, 0.f);
        o.z = fmaxf(o.z, 0.f); o.w = fmaxf(o.w, 0.f);
    }
    ((float4*)out)[node * 32 + lane] = o;
}

// ---------------- launch ----------------
extern "C" void kernel_launch(void* const* d_in, const int* in_sizes, int n_in,
                              void* d_out, int out_size) {
    const float* x    = (const float*)d_in[0];
    const int*   ei   = (const int*)  d_in[1];
    const float* Wl1  = (const float*)d_in[2];
    const float* bl1  = (const float*)d_in[3];
    const float* Wr1  = (const float*)d_in[4];
    const float* br1  = (const float*)d_in[5];
    const float* att1 = (const float*)d_in[6];
    const float* b1   = (const float*)d_in[7];
    const float* Wl2  = (const float*)d_in[8];
    const float* bl2  = (const float*)d_in[9];
    const float* Wr2  = (const float*)d_in[10];
    const float* br2  = (const float*)d_in[11];
    const float* att2 = (const float*)d_in[12];
    const float* b2   = (const float*)d_in[13];
    float* out = (float*)d_out;

    const int* src = ei;
    const int* dst = ei + NEDGES;

    static cudaStream_t s_side = nullptr;
    static cudaEvent_t  s_fork = nullptr, s_join = nullptr;
    static void* s_deg_ptr = nullptr;
    if (!s_side) {
        cudaStreamCreateWithFlags(&s_side, cudaStreamNonBlocking);
        cudaEventCreateWithFlags(&s_fork, cudaEventDisableTiming);
        cudaEventCreateWithFlags(&s_join, cudaEventDisableTiming);
        cudaGetSymbolAddress(&s_deg_ptr, g_deg);
        cudaFuncSetAttribute(gemm_mma_kernel,
                             cudaFuncAttributeMaxDynamicSharedMemorySize, SM_TOTAL);
    }

    const int ggrid = (NNODES + 127) / 128;
    const int gat_blocks = (NNODES * 32 + 255) / 256;

    // fork: CSR build on side stream, weight prep + gemm1 on main
    cudaEventRecord(s_fork, 0);
    cudaStreamWaitEvent(s_side, s_fork, 0);

    cudaMemsetAsync(s_deg_ptr, 0, NNODES * sizeof(int), s_side);
    count_kernel<<<(NEDGES + 255) / 256, 256, 0, s_side>>>(dst);
    bsum_kernel<<<NBLK, SCAN_B, 0, s_side>>>();
    bscan_kernel<<<NBLK, SCAN_B, 0, s_side>>>();
    scatter_kernel<<<(NEDGES + 255) / 256, 256, 0, s_side>>>(src, dst);
    cudaEventRecord(s_join, s_side);

    prep_w_kernel<<<4, 256>>>(Wl1, Wr1, Wl2, Wr2);
    gemm_mma_kernel<<<ggrid, 512, SM_TOTAL>>>(x, 0, 0, bl1, br1);

    cudaStreamWaitEvent(0, s_join, 0);
    gat_kernel<<<gat_blocks, 256>>>(att1, b1, out, 0, 1);
    gemm_mma_kernel<<<ggrid, 512, SM_TOTAL>>>(x, 1, 1, bl2, br2);
    gat_kernel<<<gat_blocks, 256>>>(att2, b2, out, 1, 0);
}